// round 7
// baseline (speedup 1.0000x reference)
#include <cuda_runtime.h>
#include <cuda_bf16.h>
#include <math.h>
#include <stdint.h>

// Problem constants
#define SB   2048
#define BB   2
#define DD   1024
#define NH   16
#define HDIM 64
#define MR   (BB*SB)       // 4096

// Scratch (device globals) — all attention tensors live as bf16 hi/lo splits
__device__ __align__(256) __nv_bfloat16 g_xhi[(size_t)MR*DD];
__device__ __align__(256) __nv_bfloat16 g_xlo[(size_t)MR*DD];
__device__ __align__(256) __nv_bfloat16 g_whi[4][(size_t)DD*DD];
__device__ __align__(256) __nv_bfloat16 g_wlo[4][(size_t)DD*DD];
__device__ __align__(256) __nv_bfloat16 g_qhi[(size_t)MR*DD];   // [b,h,s,hd]
__device__ __align__(256) __nv_bfloat16 g_qlo[(size_t)MR*DD];
__device__ __align__(256) __nv_bfloat16 g_khi[(size_t)MR*DD];
__device__ __align__(256) __nv_bfloat16 g_klo[(size_t)MR*DD];
__device__ __align__(256) __nv_bfloat16 g_vhi[(size_t)MR*DD];
__device__ __align__(256) __nv_bfloat16 g_vlo[(size_t)MR*DD];
__device__ __align__(256) __nv_bfloat16 g_chi[(size_t)MR*DD];   // ctx [b,s,d]
__device__ __align__(256) __nv_bfloat16 g_clo[(size_t)MR*DD];

// ===========================================================================
// Helpers
// ===========================================================================
__device__ __forceinline__ uint32_t smem_u32(const void* p) {
    uint32_t a;
    asm("{ .reg .u64 t; cvta.to.shared.u64 t, %1; cvt.u32.u64 %0, t; }"
        : "=r"(a) : "l"(p));
    return a;
}

__device__ __forceinline__ void ldsm4(uint32_t* r, uint32_t a) {
    asm volatile("ldmatrix.sync.aligned.m8n8.x4.shared.b16 {%0,%1,%2,%3}, [%4];"
                 : "=r"(r[0]), "=r"(r[1]), "=r"(r[2]), "=r"(r[3]) : "r"(a));
}

__device__ __forceinline__ void ldsm4t(uint32_t* r, uint32_t a) {
    asm volatile("ldmatrix.sync.aligned.m8n8.x4.trans.shared.b16 {%0,%1,%2,%3}, [%4];"
                 : "=r"(r[0]), "=r"(r[1]), "=r"(r[2]), "=r"(r[3]) : "r"(a));
}

__device__ __forceinline__ void mma16816(float* c, const uint32_t* a, const uint32_t* b) {
    asm volatile(
        "mma.sync.aligned.m16n8k16.row.col.f32.bf16.bf16.f32 "
        "{%0,%1,%2,%3}, {%4,%5,%6,%7}, {%8,%9}, {%0,%1,%2,%3};"
        : "+f"(c[0]), "+f"(c[1]), "+f"(c[2]), "+f"(c[3])
        : "r"(a[0]), "r"(a[1]), "r"(a[2]), "r"(a[3]), "r"(b[0]), "r"(b[1]));
}

__device__ __forceinline__ void cp16(uint32_t dst, const void* src) {
    asm volatile("cp.async.cg.shared.global [%0], [%1], 16;"
                 :: "r"(dst), "l"(src) : "memory");
}
#define CP_COMMIT asm volatile("cp.async.commit_group;" ::: "memory")
#define CP_WAIT0  asm volatile("cp.async.wait_group 0;"  ::: "memory")
#define CP_WAIT1  asm volatile("cp.async.wait_group 1;"  ::: "memory")
#define CP_WAIT2  asm volatile("cp.async.wait_group 2;"  ::: "memory")

__device__ __forceinline__ uint32_t pack2(__nv_bfloat16 a, __nv_bfloat16 b) {
    __nv_bfloat162 t = __halves2bfloat162(a, b);
    return *(uint32_t*)&t;
}

__device__ __forceinline__ uint32_t packsplit(float a, float b, uint32_t& lo) {
    __nv_bfloat16 ha = __float2bfloat16(a), hb = __float2bfloat16(b);
    lo = pack2(__float2bfloat16(a - __bfloat162float(ha)),
               __float2bfloat16(b - __bfloat162float(hb)));
    return pack2(ha, hb);
}

// ===========================================================================
// Split-convert fp32 -> bf16 hi + lo (one launch, 5 segments)
// ===========================================================================
__global__ void convert_split_all(const float* __restrict__ x,
                                  const float* __restrict__ Wq,
                                  const float* __restrict__ Wk,
                                  const float* __restrict__ Wv,
                                  const float* __restrict__ Wo)
{
    const int seg = blockIdx.y;
    const float* src;
    __nv_bfloat16 *hi, *lo;
    int n4;
    switch (seg) {
        case 0: src = x;  hi = g_xhi;    lo = g_xlo;    n4 = MR*DD/4; break;
        case 1: src = Wq; hi = g_whi[0]; lo = g_wlo[0]; n4 = DD*DD/4; break;
        case 2: src = Wk; hi = g_whi[1]; lo = g_wlo[1]; n4 = DD*DD/4; break;
        case 3: src = Wv; hi = g_whi[2]; lo = g_wlo[2]; n4 = DD*DD/4; break;
        default: src = Wo; hi = g_whi[3]; lo = g_wlo[3]; n4 = DD*DD/4; break;
    }
    for (int i = blockIdx.x * blockDim.x + threadIdx.x; i < n4;
         i += gridDim.x * blockDim.x) {
        float4 v = ((const float4*)src)[i];
        uint32_t l01, l23;
        uint32_t h01 = packsplit(v.x, v.y, l01);
        uint32_t h23 = packsplit(v.z, v.w, l23);
        ((uint2*)hi)[i] = make_uint2(h01, h23);
        ((uint2*)lo)[i] = make_uint2(l01, l23);
    }
}

// ===========================================================================
// mma.sync GEMM mainloop: 3-term split, K-step 16, 4-stage cp.async pipeline.
// Stage tile: 128 rows x 48B pitch (16 halves data, conflict-free ldsm).
// ===========================================================================
#define PITCH_B     48
#define TILE_B      (128*PITCH_B)       // 6144
#define STAGE_B     (4*TILE_B)          // 24576
#define GSMEM       (4*STAGE_B)         // 98304

__device__ __forceinline__ void gemm_mainloop(
    const __nv_bfloat16* __restrict__ Ahi, const __nv_bfloat16* __restrict__ Alo,
    const __nv_bfloat16* __restrict__ Bhi, const __nv_bfloat16* __restrict__ Blo,
    int m0, int n0, char* sm, float acc[4][4][4])
{
    const int tid = threadIdx.x;
    const uint32_t smb = smem_u32(sm);

    #pragma unroll
    for (int t = 0; t < 4; t++)
        #pragma unroll
        for (int n = 0; n < 4; n++)
            #pragma unroll
            for (int e = 0; e < 4; e++) acc[t][n][e] = 0.0f;

    const int lr = tid >> 1;          // 0..127
    const int lc = tid & 1;           // 0..1 (8-half chunk)
    auto load_stage = [&](int st, int k0) {
        uint32_t base = smb + st * STAGE_B;
        uint32_t doff = lr * PITCH_B + lc * 16;
        size_t sa = (size_t)(m0 + lr) * DD + k0 + lc*8;
        size_t sb = (size_t)(n0 + lr) * DD + k0 + lc*8;
        cp16(base + doff,            Ahi + sa);
        cp16(base + TILE_B + doff,   Alo + sa);
        cp16(base + 2*TILE_B + doff, Bhi + sb);
        cp16(base + 3*TILE_B + doff, Blo + sb);
    };

    load_stage(0, 0);  CP_COMMIT;
    load_stage(1, 16); CP_COMMIT;
    load_stage(2, 32); CP_COMMIT;

    const int wid = tid >> 5, lane = tid & 31;
    const int wm = (wid >> 2) * 64;
    const int wn = (wid & 3) * 32;
    const int arow = lane & 15;
    const int akk  = (lane >> 4) << 3;
    const int brow = (lane & 7) + ((lane >> 4) << 3);
    const int bkk  = ((lane >> 3) & 1) << 3;

    for (int kt = 0; kt < 64; kt++) {
        CP_WAIT2;              // stage kt resident (kt+1, kt+2 may be pending)
        __syncthreads();
        if (kt + 3 < 64) { load_stage((kt + 3) & 3, (kt + 3) * 16); CP_COMMIT; }

        uint32_t base = smb + (kt & 3) * STAGE_B;
        uint32_t sAh = base, sAl = base + TILE_B;
        uint32_t sBh = base + 2*TILE_B, sBl = base + 3*TILE_B;

        uint32_t ah[4][4], al[4][4], bh[4][2], bl[4][2];
        #pragma unroll
        for (int t = 0; t < 4; t++) {
            uint32_t ao = (uint32_t)((wm + t*16 + arow) * PITCH_B + akk * 2);
            ldsm4(ah[t], sAh + ao);
            ldsm4(al[t], sAl + ao);
        }
        #pragma unroll
        for (int p = 0; p < 2; p++) {
            uint32_t bo = (uint32_t)((wn + p*16 + brow) * PITCH_B + bkk * 2);
            uint32_t r4[4];
            ldsm4(r4, sBh + bo);
            bh[2*p][0] = r4[0]; bh[2*p][1] = r4[1];
            bh[2*p+1][0] = r4[2]; bh[2*p+1][1] = r4[3];
            ldsm4(r4, sBl + bo);
            bl[2*p][0] = r4[0]; bl[2*p][1] = r4[1];
            bl[2*p+1][0] = r4[2]; bl[2*p+1][1] = r4[3];
        }
        #pragma unroll
        for (int t = 0; t < 4; t++)
            #pragma unroll
            for (int n = 0; n < 4; n++)
                mma16816(acc[t][n], ah[t], bh[n]);
        #pragma unroll
        for (int t = 0; t < 4; t++)
            #pragma unroll
            for (int n = 0; n < 4; n++)
                mma16816(acc[t][n], ah[t], bl[n]);
        #pragma unroll
        for (int t = 0; t < 4; t++)
            #pragma unroll
            for (int n = 0; n < 4; n++)
                mma16816(acc[t][n], al[t], bh[n]);
    }
}

// ---------------------------------------------------------------------------
// QKV projection: writes q/k/v as bf16 hi/lo in [b,h,s,hd]
// ---------------------------------------------------------------------------
__global__ __launch_bounds__(256, 2) void qkv_gemm_mma()
{
    extern __shared__ char sm[];
    const int n0g = blockIdx.x * 128;
    const int m0  = blockIdx.y * 128;
    const int which = n0g >> 10;
    const int nb    = n0g & 1023;

    __nv_bfloat16* OH = (which == 0) ? g_qhi : (which == 1 ? g_khi : g_vhi);
    __nv_bfloat16* OL = (which == 0) ? g_qlo : (which == 1 ? g_klo : g_vlo);

    float acc[4][4][4];
    gemm_mainloop(g_xhi, g_xlo, g_whi[which], g_wlo[which], m0, nb, sm, acc);

    const int tid = threadIdx.x, wid = tid >> 5, lane = tid & 31;
    const int wm = (wid >> 2) * 64, wn = (wid & 3) * 32;
    const int gid = lane >> 2, qid = lane & 3;

    #pragma unroll
    for (int t = 0; t < 4; t++) {
        #pragma unroll
        for (int n = 0; n < 4; n++) {
            int cc = nb + wn + n*8 + qid*2;
            int h = cc >> 6, hd = cc & 63;
            #pragma unroll
            for (int half = 0; half < 2; half++) {
                int row = m0 + wm + t*16 + gid + 8*half;
                int b = row >> 11, s = row & 2047;
                uint32_t lo;
                uint32_t hi = packsplit(acc[t][n][2*half], acc[t][n][2*half+1], lo);
                size_t off = (((size_t)(b*NH + h))*SB + s)*HDIM + hd;
                *(uint32_t*)&OH[off] = hi;
                *(uint32_t*)&OL[off] = lo;
            }
        }
    }
}

// ---------------------------------------------------------------------------
// Output projection: out = ctx @ Wo^T + bo (fp32 out)
// ---------------------------------------------------------------------------
__global__ __launch_bounds__(256, 2) void out_gemm_mma(
    const float* __restrict__ bo, float* __restrict__ OUT)
{
    extern __shared__ char sm[];
    const int n0 = blockIdx.x * 128;
    const int m0 = blockIdx.y * 128;

    float acc[4][4][4];
    gemm_mainloop(g_chi, g_clo, g_whi[3], g_wlo[3], m0, n0, sm, acc);

    const int tid = threadIdx.x, wid = tid >> 5, lane = tid & 31;
    const int wm = (wid >> 2) * 64, wn = (wid & 3) * 32;
    const int gid = lane >> 2, qid = lane & 3;

    #pragma unroll
    for (int t = 0; t < 4; t++) {
        #pragma unroll
        for (int n = 0; n < 4; n++) {
            int cn = n0 + wn + n*8 + qid*2;
            float2 bb = *(const float2*)&bo[cn];
            #pragma unroll
            for (int half = 0; half < 2; half++) {
                int row = m0 + wm + t*16 + gid + 8*half;
                float2 v = make_float2(acc[t][n][2*half] + bb.x,
                                       acc[t][n][2*half + 1] + bb.y);
                *(float2*)&OUT[(size_t)row * DD + cn] = v;
            }
        }
    }
}

// ===========================================================================
// Flash attention on mma.sync (FA2-style, 3-term bf16 split).
// 128 q-rows per CTA (8 warps x 16 rows), 64-key steps.
// 3 KV stages (wait_group 1, prefetch 2 ahead). Q borrows stage-2's buffer:
// consumed into register fragments before kv2 is issued (kt=0 barrier guards).
// ===========================================================================
#define FP_B  144                    // smem pitch bytes (72 halves)
#define BUF_B  (64*FP_B)             // 9216
#define STG_B  (4*BUF_B)             // 36864
#define FA_SMEM (3*STG_B)            // 110592

__global__ __launch_bounds__(256, 2) void flash_attn_mma()
{
    extern __shared__ char smc[];
    const uint32_t smb = smem_u32(smc);

    const int qt = (int)gridDim.x - 1 - (int)blockIdx.x;   // heavy first
    const int bh = blockIdx.y;
    const int q0 = qt * 128;

    const int tid = threadIdx.x, w = tid >> 5, lane = tid & 31;
    const int wm = w * 16;

    const __nv_bfloat16* Qph = g_qhi + ((size_t)bh*SB + q0)*HDIM;
    const __nv_bfloat16* Qpl = g_qlo + ((size_t)bh*SB + q0)*HDIM;
    const __nv_bfloat16* Kph = g_khi + (size_t)bh*SB*HDIM;
    const __nv_bfloat16* Kpl = g_klo + (size_t)bh*SB*HDIM;
    const __nv_bfloat16* Vph = g_vhi + (size_t)bh*SB*HDIM;
    const __nv_bfloat16* Vpl = g_vlo + (size_t)bh*SB*HDIM;

    // ---- load Q (hi+lo) into stage-2 buffer ----
    const uint32_t QH_OFF = 2*STG_B;
    const uint32_t QL_OFF = 2*STG_B + 128*FP_B;
    for (int idx = tid; idx < 2048; idx += 256) {
        int buf = idx >> 10, r = (idx >> 3) & 127, c = idx & 7;
        cp16(smb + (buf ? QL_OFF : QH_OFF) + r*FP_B + c*16,
             (buf ? Qpl : Qph) + r*64 + c*8);
    }
    CP_COMMIT;

    auto load_kv = [&](int st, int c0) {
        uint32_t base = smb + st*STG_B;
        for (int idx = tid; idx < 2048; idx += 256) {
            int buf = idx >> 9, r = (idx >> 3) & 63, c = idx & 7;
            const __nv_bfloat16* sp =
                (buf == 0 ? Kph : buf == 1 ? Kpl : buf == 2 ? Vph : Vpl)
                + (size_t)(c0 + r)*64 + c*8;
            cp16(base + buf*BUF_B + r*FP_B + c*16, sp);
        }
    };

    const int nsteps = 2*(qt + 1);     // >= 2 always
    load_kv(0, 0);  CP_COMMIT;
    load_kv(1, 64); CP_COMMIT;

    // Q done (kv0, kv1 may still be pending)
    CP_WAIT2;
    __syncthreads();

    const int arow = lane & 15;
    const int akk  = (lane >> 4) << 3;
    uint32_t qa[2][4][4];
    #pragma unroll
    for (int term = 0; term < 2; term++)
        #pragma unroll
        for (int t = 0; t < 4; t++)
            ldsm4(qa[term][t], smb + (term ? QL_OFF : QH_OFF)
                              + (wm + arow)*FP_B + (t*16 + akk)*2);

    float m0v = -INFINITY, m1v = -INFINITY, l0v = 0.0f, l1v = 0.0f;
    float oc[8][4];
    #pragma unroll
    for (int j = 0; j < 8; j++)
        #pragma unroll
        for (int e = 0; e < 4; e++) oc[j][e] = 0.0f;

    const int brow = (lane & 7) + ((lane >> 4) << 3);
    const int bkk  = ((lane >> 3) & 1) << 3;
    const int vrow = (lane & 7) + (((lane >> 3) & 1) << 3);
    const int vc8  = (lane >> 4) << 3;

    int stage = 0;                      // kt % 3
    for (int kt = 0; kt < nsteps; kt++) {
        const int c0 = kt * 64;
        CP_WAIT1;                       // kv[kt] resident (kv[kt+1] pending)
        __syncthreads();                // also: all warps done with buf being reloaded
        if (kt + 2 < nsteps) {
            int st2 = stage + 2; if (st2 >= 3) st2 -= 3;
            load_kv(st2, (kt + 2)*64);
            CP_COMMIT;
        }

        const uint32_t sKh = smb + stage*STG_B;
        const uint32_t sKl = sKh + BUF_B;
        const uint32_t sVh = sKh + 2*BUF_B;
        const uint32_t sVl = sKh + 3*BUF_B;

        // ---- S = Q K^T ----
        float sc[8][4];
        #pragma unroll
        for (int j = 0; j < 8; j++)
            #pragma unroll
            for (int e = 0; e < 4; e++) sc[j][e] = 0.0f;

        #pragma unroll
        for (int k16 = 0; k16 < 4; k16++) {
            uint32_t kh[8][2], kl[8][2];
            #pragma unroll
            for (int j2 = 0; j2 < 4; j2++) {
                uint32_t off = (uint32_t)((j2*16 + brow)*FP_B + (k16*16 + bkk)*2);
                uint32_t r4[4];
                ldsm4(r4, sKh + off);
                kh[2*j2][0] = r4[0]; kh[2*j2][1] = r4[1];
                kh[2*j2+1][0] = r4[2]; kh[2*j2+1][1] = r4[3];
                ldsm4(r4, sKl + off);
                kl[2*j2][0] = r4[0]; kl[2*j2][1] = r4[1];
                kl[2*j2+1][0] = r4[2]; kl[2*j2+1][1] = r4[3];
            }
            #pragma unroll
            for (int j = 0; j < 8; j++) mma16816(sc[j], qa[0][k16], kh[j]);
            #pragma unroll
            for (int j = 0; j < 8; j++) mma16816(sc[j], qa[0][k16], kl[j]);
            #pragma unroll
            for (int j = 0; j < 8; j++) mma16816(sc[j], qa[1][k16], kh[j]);
        }

        // ---- scale + causal mask ----
        const int r0 = q0 + wm + (lane >> 2);
        const bool needmask = (c0 + 64 > q0 + wm);
        #pragma unroll
        for (int j = 0; j < 8; j++) {
            int cb = c0 + j*8 + (lane & 3)*2;
            #pragma unroll
            for (int e = 0; e < 4; e++) {
                float v = sc[j][e] * 0.125f;
                if (needmask) {
                    int col = cb + (e & 1);
                    int row = r0 + ((e >> 1) << 3);
                    if (col > row) v = -INFINITY;
                }
                sc[j][e] = v;
            }
        }

        // ---- online softmax ----
        float mx0 = sc[0][0], mx1 = sc[0][2];
        #pragma unroll
        for (int j = 0; j < 8; j++) {
            mx0 = fmaxf(mx0, fmaxf(sc[j][0], sc[j][1]));
            mx1 = fmaxf(mx1, fmaxf(sc[j][2], sc[j][3]));
        }
        mx0 = fmaxf(mx0, __shfl_xor_sync(0xffffffffu, mx0, 1));
        mx0 = fmaxf(mx0, __shfl_xor_sync(0xffffffffu, mx0, 2));
        mx1 = fmaxf(mx1, __shfl_xor_sync(0xffffffffu, mx1, 1));
        mx1 = fmaxf(mx1, __shfl_xor_sync(0xffffffffu, mx1, 2));

        float mn0 = fmaxf(m0v, mx0), mn1 = fmaxf(m1v, mx1);
        float al0 = __expf(m0v - mn0), al1 = __expf(m1v - mn1);
        m0v = mn0; m1v = mn1;

        float s0 = 0.0f, s1 = 0.0f;
        #pragma unroll
        for (int j = 0; j < 8; j++) {
            sc[j][0] = __expf(sc[j][0] - mn0); s0 += sc[j][0];
            sc[j][1] = __expf(sc[j][1] - mn0); s0 += sc[j][1];
            sc[j][2] = __expf(sc[j][2] - mn1); s1 += sc[j][2];
            sc[j][3] = __expf(sc[j][3] - mn1); s1 += sc[j][3];
        }
        s0 += __shfl_xor_sync(0xffffffffu, s0, 1);
        s0 += __shfl_xor_sync(0xffffffffu, s0, 2);
        s1 += __shfl_xor_sync(0xffffffffu, s1, 1);
        s1 += __shfl_xor_sync(0xffffffffu, s1, 2);
        l0v = l0v * al0 + s0;
        l1v = l1v * al1 + s1;
        #pragma unroll
        for (int j = 0; j < 8; j++) {
            oc[j][0] *= al0; oc[j][1] *= al0;
            oc[j][2] *= al1; oc[j][3] *= al1;
        }

        // ---- repack P (C-frag == A-frag layout) ----
        uint32_t pah[4][4], pal[4][4];
        #pragma unroll
        for (int t = 0; t < 4; t++) {
            pah[t][0] = packsplit(sc[2*t][0],   sc[2*t][1],   pal[t][0]);
            pah[t][1] = packsplit(sc[2*t][2],   sc[2*t][3],   pal[t][1]);
            pah[t][2] = packsplit(sc[2*t+1][0], sc[2*t+1][1], pal[t][2]);
            pah[t][3] = packsplit(sc[2*t+1][2], sc[2*t+1][3], pal[t][3]);
        }

        // ---- O += P V ----
        #pragma unroll
        for (int k16 = 0; k16 < 4; k16++) {
            uint32_t vh[8][2], vl[8][2];
            #pragma unroll
            for (int n16 = 0; n16 < 4; n16++) {
                uint32_t off = (uint32_t)((k16*16 + vrow)*FP_B + (n16*16 + vc8)*2);
                uint32_t r4[4];
                ldsm4t(r4, sVh + off);
                vh[2*n16][0] = r4[0]; vh[2*n16][1] = r4[1];
                vh[2*n16+1][0] = r4[2]; vh[2*n16+1][1] = r4[3];
                ldsm4t(r4, sVl + off);
                vl[2*n16][0] = r4[0]; vl[2*n16][1] = r4[1];
                vl[2*n16+1][0] = r4[2]; vl[2*n16+1][1] = r4[3];
            }
            #pragma unroll
            for (int j = 0; j < 8; j++) mma16816(oc[j], pah[k16], vh[j]);
            #pragma unroll
            for (int j = 0; j < 8; j++) mma16816(oc[j], pah[k16], vl[j]);
            #pragma unroll
            for (int j = 0; j < 8; j++) mma16816(oc[j], pal[k16], vh[j]);
        }

        if (++stage == 3) stage = 0;
    }

    // ---- finalize, write ctx bf16 hi/lo ----
    const float inv0 = 1.0f / l0v, inv1 = 1.0f / l1v;
    const int b = bh / NH, h = bh % NH;
    const int row0 = q0 + wm + (lane >> 2);
    #pragma unroll
    for (int j = 0; j < 8; j++) {
        int col = h*64 + j*8 + (lane & 3)*2;
        uint32_t lo;
        uint32_t hi = packsplit(oc[j][0]*inv0, oc[j][1]*inv0, lo);
        size_t off0 = ((size_t)(b*SB + row0))*DD + col;
        *(uint32_t*)&g_chi[off0] = hi;
        *(uint32_t*)&g_clo[off0] = lo;
        hi = packsplit(oc[j][2]*inv1, oc[j][3]*inv1, lo);
        size_t off1 = ((size_t)(b*SB + row0 + 8))*DD + col;
        *(uint32_t*)&g_chi[off1] = hi;
        *(uint32_t*)&g_clo[off1] = lo;
    }
}

// ---------------------------------------------------------------------------
extern "C" void kernel_launch(void* const* d_in, const int* in_sizes, int n_in,
                              void* d_out, int out_size)
{
    const float* x  = (const float*)d_in[0];
    const float* Wq = (const float*)d_in[1];
    const float* Wk = (const float*)d_in[2];
    const float* Wv = (const float*)d_in[3];
    const float* Wo = (const float*)d_in[4];
    const float* bo = (const float*)d_in[5];
    float* out = (float*)d_out;

    cudaFuncSetAttribute(qkv_gemm_mma,   cudaFuncAttributeMaxDynamicSharedMemorySize, GSMEM);
    cudaFuncSetAttribute(out_gemm_mma,   cudaFuncAttributeMaxDynamicSharedMemorySize, GSMEM);
    cudaFuncSetAttribute(flash_attn_mma, cudaFuncAttributeMaxDynamicSharedMemorySize, FA_SMEM);

    convert_split_all<<<dim3(160, 5), 256>>>(x, Wq, Wk, Wv, Wo);
    qkv_gemm_mma<<<dim3(24, 32), 256, GSMEM>>>();
    flash_attn_mma<<<dim3(SB/128, BB*NH), 256, FA_SMEM>>>();
    out_gemm_mma<<<dim3(8, 32), 256, GSMEM>>>(bo, out);
}

// round 9
// speedup vs baseline: 1.1762x; 1.1762x over previous
#include <cuda_runtime.h>
#include <cuda_bf16.h>
#include <math.h>
#include <stdint.h>

// Problem constants
#define SB   2048
#define BB   2
#define DD   1024
#define NH   16
#define HDIM 64
#define MR   (BB*SB)       // 4096

// Scratch (device globals) — all attention tensors live as bf16 hi/lo splits
__device__ __align__(256) __nv_bfloat16 g_xhi[(size_t)MR*DD];
__device__ __align__(256) __nv_bfloat16 g_xlo[(size_t)MR*DD];
__device__ __align__(256) __nv_bfloat16 g_whi[4][(size_t)DD*DD];
__device__ __align__(256) __nv_bfloat16 g_wlo[4][(size_t)DD*DD];
__device__ __align__(256) __nv_bfloat16 g_qhi[(size_t)MR*DD];   // [b,h,s,hd]
__device__ __align__(256) __nv_bfloat16 g_qlo[(size_t)MR*DD];
__device__ __align__(256) __nv_bfloat16 g_khi[(size_t)MR*DD];
__device__ __align__(256) __nv_bfloat16 g_klo[(size_t)MR*DD];
__device__ __align__(256) __nv_bfloat16 g_vhi[(size_t)MR*DD];
__device__ __align__(256) __nv_bfloat16 g_vlo[(size_t)MR*DD];
__device__ __align__(256) __nv_bfloat16 g_chi[(size_t)MR*DD];   // ctx [b,s,d]
__device__ __align__(256) __nv_bfloat16 g_clo[(size_t)MR*DD];

// ===========================================================================
// Helpers
// ===========================================================================
__device__ __forceinline__ uint32_t smem_u32(const void* p) {
    uint32_t a;
    asm("{ .reg .u64 t; cvta.to.shared.u64 t, %1; cvt.u32.u64 %0, t; }"
        : "=r"(a) : "l"(p));
    return a;
}

__device__ __forceinline__ void ldsm4(uint32_t* r, uint32_t a) {
    asm volatile("ldmatrix.sync.aligned.m8n8.x4.shared.b16 {%0,%1,%2,%3}, [%4];"
                 : "=r"(r[0]), "=r"(r[1]), "=r"(r[2]), "=r"(r[3]) : "r"(a));
}

__device__ __forceinline__ void ldsm4t(uint32_t* r, uint32_t a) {
    asm volatile("ldmatrix.sync.aligned.m8n8.x4.trans.shared.b16 {%0,%1,%2,%3}, [%4];"
                 : "=r"(r[0]), "=r"(r[1]), "=r"(r[2]), "=r"(r[3]) : "r"(a));
}

__device__ __forceinline__ void mma16816(float* c, const uint32_t* a, const uint32_t* b) {
    asm volatile(
        "mma.sync.aligned.m16n8k16.row.col.f32.bf16.bf16.f32 "
        "{%0,%1,%2,%3}, {%4,%5,%6,%7}, {%8,%9}, {%0,%1,%2,%3};"
        : "+f"(c[0]), "+f"(c[1]), "+f"(c[2]), "+f"(c[3])
        : "r"(a[0]), "r"(a[1]), "r"(a[2]), "r"(a[3]), "r"(b[0]), "r"(b[1]));
}

__device__ __forceinline__ void cp16(uint32_t dst, const void* src) {
    asm volatile("cp.async.cg.shared.global [%0], [%1], 16;"
                 :: "r"(dst), "l"(src) : "memory");
}
#define CP_COMMIT asm volatile("cp.async.commit_group;" ::: "memory")
#define CP_WAIT0  asm volatile("cp.async.wait_group 0;"  ::: "memory")
#define CP_WAIT1  asm volatile("cp.async.wait_group 1;"  ::: "memory")
#define CP_WAIT2  asm volatile("cp.async.wait_group 2;"  ::: "memory")

__device__ __forceinline__ uint32_t pack2(__nv_bfloat16 a, __nv_bfloat16 b) {
    __nv_bfloat162 t = __halves2bfloat162(a, b);
    return *(uint32_t*)&t;
}

__device__ __forceinline__ uint32_t packsplit(float a, float b, uint32_t& lo) {
    __nv_bfloat16 ha = __float2bfloat16(a), hb = __float2bfloat16(b);
    lo = pack2(__float2bfloat16(a - __bfloat162float(ha)),
               __float2bfloat16(b - __bfloat162float(hb)));
    return pack2(ha, hb);
}

// ===========================================================================
// Split-convert fp32 -> bf16 hi + lo (one launch, 5 segments)
// ===========================================================================
__global__ void convert_split_all(const float* __restrict__ x,
                                  const float* __restrict__ Wq,
                                  const float* __restrict__ Wk,
                                  const float* __restrict__ Wv,
                                  const float* __restrict__ Wo)
{
    const int seg = blockIdx.y;
    const float* src;
    __nv_bfloat16 *hi, *lo;
    int n4;
    switch (seg) {
        case 0: src = x;  hi = g_xhi;    lo = g_xlo;    n4 = MR*DD/4; break;
        case 1: src = Wq; hi = g_whi[0]; lo = g_wlo[0]; n4 = DD*DD/4; break;
        case 2: src = Wk; hi = g_whi[1]; lo = g_wlo[1]; n4 = DD*DD/4; break;
        case 3: src = Wv; hi = g_whi[2]; lo = g_wlo[2]; n4 = DD*DD/4; break;
        default: src = Wo; hi = g_whi[3]; lo = g_wlo[3]; n4 = DD*DD/4; break;
    }
    for (int i = blockIdx.x * blockDim.x + threadIdx.x; i < n4;
         i += gridDim.x * blockDim.x) {
        float4 v = ((const float4*)src)[i];
        uint32_t l01, l23;
        uint32_t h01 = packsplit(v.x, v.y, l01);
        uint32_t h23 = packsplit(v.z, v.w, l23);
        ((uint2*)hi)[i] = make_uint2(h01, h23);
        ((uint2*)lo)[i] = make_uint2(l01, l23);
    }
}

// ===========================================================================
// mma.sync GEMM mainloop: 3-term split, K-step 32, 3-stage cp.async pipeline
// (wait_group 1 -> ~2 iterations of load slack, one sync per iteration).
// Stage tile: 128 rows x 64B (32 halves, no padding) with XOR swizzle:
//   physical 16B-chunk = c ^ ((row>>1)&3)
// -> all ldmatrix lane addresses 16B-aligned; for the 8 rows of any 8x8
//    matrix, bank-slot (row&1)*4 + phys is a bijection onto 0..7 (no conflicts).
// ===========================================================================
#define GP_B        64
#define TILE_B      (128*GP_B)          // 8192
#define STAGE_B     (4*TILE_B)          // 32768
#define GSMEM       (3*STAGE_B)         // 98304

__device__ __forceinline__ uint32_t gsw(int row, int chunk) {
    return (uint32_t)(row * GP_B + ((chunk ^ ((row >> 1) & 3)) << 4));
}

__device__ __forceinline__ void gemm_mainloop(
    const __nv_bfloat16* __restrict__ Ahi, const __nv_bfloat16* __restrict__ Alo,
    const __nv_bfloat16* __restrict__ Bhi, const __nv_bfloat16* __restrict__ Blo,
    int m0, int n0, char* sm, float acc[4][4][4])
{
    const int tid = threadIdx.x;
    const uint32_t smb = smem_u32(sm);

    #pragma unroll
    for (int t = 0; t < 4; t++)
        #pragma unroll
        for (int n = 0; n < 4; n++)
            #pragma unroll
            for (int e = 0; e < 4; e++) acc[t][n][e] = 0.0f;

    auto load_stage = [&](int st, int k0) {
        uint32_t base = smb + st * STAGE_B;
        #pragma unroll
        for (int j = 0; j < 2; j++) {
            int idx = tid + j * 256;
            int r = idx >> 2, c = idx & 3;
            uint32_t doff = gsw(r, c);
            size_t sa = (size_t)(m0 + r) * DD + k0 + c * 8;
            size_t sb = (size_t)(n0 + r) * DD + k0 + c * 8;
            cp16(base + doff,            Ahi + sa);
            cp16(base + TILE_B + doff,   Alo + sa);
            cp16(base + 2*TILE_B + doff, Bhi + sb);
            cp16(base + 3*TILE_B + doff, Blo + sb);
        }
    };

    load_stage(0, 0);  CP_COMMIT;
    load_stage(1, 32); CP_COMMIT;

    const int wid = tid >> 5, lane = tid & 31;
    const int wm = (wid >> 2) * 64;
    const int wn = (wid & 3) * 32;
    const int arow = lane & 15;
    const int ack  = lane >> 4;            // A chunk lsb (0/1)
    const int brow = (lane & 7) + ((lane >> 4) << 3);
    const int bck  = (lane >> 3) & 1;      // B chunk lsb (0/1)

    int stage = 0;
    for (int kt = 0; kt < 32; kt++) {
        CP_WAIT1;              // stage kt resident; stage kt+1 may be pending
        __syncthreads();       // all warps done reading the stage we overwrite
        if (kt + 2 < 32) {
            int st2 = stage + 2; if (st2 >= 3) st2 -= 3;
            load_stage(st2, (kt + 2) * 32);
            CP_COMMIT;
        }

        uint32_t base = smb + stage * STAGE_B;
        uint32_t sAh = base, sAl = base + TILE_B;
        uint32_t sBh = base + 2*TILE_B, sBl = base + 3*TILE_B;

        #pragma unroll
        for (int k16 = 0; k16 < 2; k16++) {
            uint32_t ah[4][4], al[4][4], bh[4][2], bl[4][2];
            #pragma unroll
            for (int t = 0; t < 4; t++) {
                uint32_t ao = gsw(wm + t*16 + arow, k16*2 + ack);
                ldsm4(ah[t], sAh + ao);
                ldsm4(al[t], sAl + ao);
            }
            #pragma unroll
            for (int p = 0; p < 2; p++) {
                uint32_t bo = gsw(wn + p*16 + brow, k16*2 + bck);
                uint32_t r4[4];
                ldsm4(r4, sBh + bo);
                bh[2*p][0] = r4[0]; bh[2*p][1] = r4[1];
                bh[2*p+1][0] = r4[2]; bh[2*p+1][1] = r4[3];
                ldsm4(r4, sBl + bo);
                bl[2*p][0] = r4[0]; bl[2*p][1] = r4[1];
                bl[2*p+1][0] = r4[2]; bl[2*p+1][1] = r4[3];
            }
            #pragma unroll
            for (int t = 0; t < 4; t++)
                #pragma unroll
                for (int n = 0; n < 4; n++)
                    mma16816(acc[t][n], ah[t], bh[n]);
            #pragma unroll
            for (int t = 0; t < 4; t++)
                #pragma unroll
                for (int n = 0; n < 4; n++)
                    mma16816(acc[t][n], ah[t], bl[n]);
            #pragma unroll
            for (int t = 0; t < 4; t++)
                #pragma unroll
                for (int n = 0; n < 4; n++)
                    mma16816(acc[t][n], al[t], bh[n]);
        }

        if (++stage == 3) stage = 0;
    }
}

// ---------------------------------------------------------------------------
// QKV projection: writes q/k/v as bf16 hi/lo in [b,h,s,hd]
// ---------------------------------------------------------------------------
__global__ __launch_bounds__(256, 2) void qkv_gemm_mma()
{
    extern __shared__ char sm[];
    const int n0g = blockIdx.x * 128;
    const int m0  = blockIdx.y * 128;
    const int which = n0g >> 10;
    const int nb    = n0g & 1023;

    __nv_bfloat16* OH = (which == 0) ? g_qhi : (which == 1 ? g_khi : g_vhi);
    __nv_bfloat16* OL = (which == 0) ? g_qlo : (which == 1 ? g_klo : g_vlo);

    float acc[4][4][4];
    gemm_mainloop(g_xhi, g_xlo, g_whi[which], g_wlo[which], m0, nb, sm, acc);

    const int tid = threadIdx.x, wid = tid >> 5, lane = tid & 31;
    const int wm = (wid >> 2) * 64, wn = (wid & 3) * 32;
    const int gid = lane >> 2, qid = lane & 3;

    #pragma unroll
    for (int t = 0; t < 4; t++) {
        #pragma unroll
        for (int n = 0; n < 4; n++) {
            int cc = nb + wn + n*8 + qid*2;
            int h = cc >> 6, hd = cc & 63;
            #pragma unroll
            for (int half = 0; half < 2; half++) {
                int row = m0 + wm + t*16 + gid + 8*half;
                int b = row >> 11, s = row & 2047;
                uint32_t lo;
                uint32_t hi = packsplit(acc[t][n][2*half], acc[t][n][2*half+1], lo);
                size_t off = (((size_t)(b*NH + h))*SB + s)*HDIM + hd;
                *(uint32_t*)&OH[off] = hi;
                *(uint32_t*)&OL[off] = lo;
            }
        }
    }
}

// ---------------------------------------------------------------------------
// Output projection: out = ctx @ Wo^T + bo (fp32 out)
// ---------------------------------------------------------------------------
__global__ __launch_bounds__(256, 2) void out_gemm_mma(
    const float* __restrict__ bo, float* __restrict__ OUT)
{
    extern __shared__ char sm[];
    const int n0 = blockIdx.x * 128;
    const int m0 = blockIdx.y * 128;

    float acc[4][4][4];
    gemm_mainloop(g_chi, g_clo, g_whi[3], g_wlo[3], m0, n0, sm, acc);

    const int tid = threadIdx.x, wid = tid >> 5, lane = tid & 31;
    const int wm = (wid >> 2) * 64, wn = (wid & 3) * 32;
    const int gid = lane >> 2, qid = lane & 3;

    #pragma unroll
    for (int t = 0; t < 4; t++) {
        #pragma unroll
        for (int n = 0; n < 4; n++) {
            int cn = n0 + wn + n*8 + qid*2;
            float2 bb = *(const float2*)&bo[cn];
            #pragma unroll
            for (int half = 0; half < 2; half++) {
                int row = m0 + wm + t*16 + gid + 8*half;
                float2 v = make_float2(acc[t][n][2*half] + bb.x,
                                       acc[t][n][2*half + 1] + bb.y);
                *(float2*)&OUT[(size_t)row * DD + cn] = v;
            }
        }
    }
}

// ===========================================================================
// Flash attention on mma.sync (FA2-style, 3-term bf16 split).
// 128 q-rows per CTA (8 warps x 16 rows), 64-key steps.
// 3 KV stages (wait_group 1, prefetch 2 ahead). Q borrows stage-2's buffer.
// ===========================================================================
#define FP_B  144                    // smem pitch bytes (72 halves, 16B mult)
#define BUF_B  (64*FP_B)             // 9216
#define STG_B  (4*BUF_B)             // 36864
#define FA_SMEM (3*STG_B)            // 110592

__global__ __launch_bounds__(256, 2) void flash_attn_mma()
{
    extern __shared__ char smc[];
    const uint32_t smb = smem_u32(smc);

    const int qt = (int)gridDim.x - 1 - (int)blockIdx.x;   // heavy first
    const int bh = blockIdx.y;
    const int q0 = qt * 128;

    const int tid = threadIdx.x, w = tid >> 5, lane = tid & 31;
    const int wm = w * 16;

    const __nv_bfloat16* Qph = g_qhi + ((size_t)bh*SB + q0)*HDIM;
    const __nv_bfloat16* Qpl = g_qlo + ((size_t)bh*SB + q0)*HDIM;
    const __nv_bfloat16* Kph = g_khi + (size_t)bh*SB*HDIM;
    const __nv_bfloat16* Kpl = g_klo + (size_t)bh*SB*HDIM;
    const __nv_bfloat16* Vph = g_vhi + (size_t)bh*SB*HDIM;
    const __nv_bfloat16* Vpl = g_vlo + (size_t)bh*SB*HDIM;

    // ---- load Q (hi+lo) into stage-2 buffer ----
    const uint32_t QH_OFF = 2*STG_B;
    const uint32_t QL_OFF = 2*STG_B + 128*FP_B;
    for (int idx = tid; idx < 2048; idx += 256) {
        int buf = idx >> 10, r = (idx >> 3) & 127, c = idx & 7;
        cp16(smb + (buf ? QL_OFF : QH_OFF) + r*FP_B + c*16,
             (buf ? Qpl : Qph) + r*64 + c*8);
    }
    CP_COMMIT;

    auto load_kv = [&](int st, int c0) {
        uint32_t base = smb + st*STG_B;
        for (int idx = tid; idx < 2048; idx += 256) {
            int buf = idx >> 9, r = (idx >> 3) & 63, c = idx & 7;
            const __nv_bfloat16* sp =
                (buf == 0 ? Kph : buf == 1 ? Kpl : buf == 2 ? Vph : Vpl)
                + (size_t)(c0 + r)*64 + c*8;
            cp16(base + buf*BUF_B + r*FP_B + c*16, sp);
        }
    };

    const int nsteps = 2*(qt + 1);     // >= 2 always
    load_kv(0, 0);  CP_COMMIT;
    load_kv(1, 64); CP_COMMIT;

    // Q done (kv0, kv1 may still be pending)
    CP_WAIT2;
    __syncthreads();

    const int arow = lane & 15;
    const int akk  = (lane >> 4) << 3;
    uint32_t qa[2][4][4];
    #pragma unroll
    for (int term = 0; term < 2; term++)
        #pragma unroll
        for (int t = 0; t < 4; t++)
            ldsm4(qa[term][t], smb + (term ? QL_OFF : QH_OFF)
                              + (wm + arow)*FP_B + (t*16 + akk)*2);

    float m0v = -INFINITY, m1v = -INFINITY, l0v = 0.0f, l1v = 0.0f;
    float oc[8][4];
    #pragma unroll
    for (int j = 0; j < 8; j++)
        #pragma unroll
        for (int e = 0; e < 4; e++) oc[j][e] = 0.0f;

    const int brow = (lane & 7) + ((lane >> 4) << 3);
    const int bkk  = ((lane >> 3) & 1) << 3;
    const int vrow = (lane & 7) + (((lane >> 3) & 1) << 3);
    const int vc8  = (lane >> 4) << 3;

    int stage = 0;                      // kt % 3
    for (int kt = 0; kt < nsteps; kt++) {
        const int c0 = kt * 64;
        CP_WAIT1;                       // kv[kt] resident (kv[kt+1] pending)
        __syncthreads();
        if (kt + 2 < nsteps) {
            int st2 = stage + 2; if (st2 >= 3) st2 -= 3;
            load_kv(st2, (kt + 2)*64);
            CP_COMMIT;
        }

        const uint32_t sKh = smb + stage*STG_B;
        const uint32_t sKl = sKh + BUF_B;
        const uint32_t sVh = sKh + 2*BUF_B;
        const uint32_t sVl = sKh + 3*BUF_B;

        // ---- S = Q K^T ----
        float sc[8][4];
        #pragma unroll
        for (int j = 0; j < 8; j++)
            #pragma unroll
            for (int e = 0; e < 4; e++) sc[j][e] = 0.0f;

        #pragma unroll
        for (int k16 = 0; k16 < 4; k16++) {
            uint32_t kh[8][2], kl[8][2];
            #pragma unroll
            for (int j2 = 0; j2 < 4; j2++) {
                uint32_t off = (uint32_t)((j2*16 + brow)*FP_B + (k16*16 + bkk)*2);
                uint32_t r4[4];
                ldsm4(r4, sKh + off);
                kh[2*j2][0] = r4[0]; kh[2*j2][1] = r4[1];
                kh[2*j2+1][0] = r4[2]; kh[2*j2+1][1] = r4[3];
                ldsm4(r4, sKl + off);
                kl[2*j2][0] = r4[0]; kl[2*j2][1] = r4[1];
                kl[2*j2+1][0] = r4[2]; kl[2*j2+1][1] = r4[3];
            }
            #pragma unroll
            for (int j = 0; j < 8; j++) mma16816(sc[j], qa[0][k16], kh[j]);
            #pragma unroll
            for (int j = 0; j < 8; j++) mma16816(sc[j], qa[0][k16], kl[j]);
            #pragma unroll
            for (int j = 0; j < 8; j++) mma16816(sc[j], qa[1][k16], kh[j]);
        }

        // ---- scale + causal mask ----
        const int r0 = q0 + wm + (lane >> 2);
        const bool needmask = (c0 + 64 > q0 + wm);
        #pragma unroll
        for (int j = 0; j < 8; j++) {
            int cb = c0 + j*8 + (lane & 3)*2;
            #pragma unroll
            for (int e = 0; e < 4; e++) {
                float v = sc[j][e] * 0.125f;
                if (needmask) {
                    int col = cb + (e & 1);
                    int row = r0 + ((e >> 1) << 3);
                    if (col > row) v = -INFINITY;
                }
                sc[j][e] = v;
            }
        }

        // ---- online softmax ----
        float mx0 = sc[0][0], mx1 = sc[0][2];
        #pragma unroll
        for (int j = 0; j < 8; j++) {
            mx0 = fmaxf(mx0, fmaxf(sc[j][0], sc[j][1]));
            mx1 = fmaxf(mx1, fmaxf(sc[j][2], sc[j][3]));
        }
        mx0 = fmaxf(mx0, __shfl_xor_sync(0xffffffffu, mx0, 1));
        mx0 = fmaxf(mx0, __shfl_xor_sync(0xffffffffu, mx0, 2));
        mx1 = fmaxf(mx1, __shfl_xor_sync(0xffffffffu, mx1, 1));
        mx1 = fmaxf(mx1, __shfl_xor_sync(0xffffffffu, mx1, 2));

        float mn0 = fmaxf(m0v, mx0), mn1 = fmaxf(m1v, mx1);
        float al0 = __expf(m0v - mn0), al1 = __expf(m1v - mn1);
        m0v = mn0; m1v = mn1;

        float s0 = 0.0f, s1 = 0.0f;
        #pragma unroll
        for (int j = 0; j < 8; j++) {
            sc[j][0] = __expf(sc[j][0] - mn0); s0 += sc[j][0];
            sc[j][1] = __expf(sc[j][1] - mn0); s0 += sc[j][1];
            sc[j][2] = __expf(sc[j][2] - mn1); s1 += sc[j][2];
            sc[j][3] = __expf(sc[j][3] - mn1); s1 += sc[j][3];
        }
        s0 += __shfl_xor_sync(0xffffffffu, s0, 1);
        s0 += __shfl_xor_sync(0xffffffffu, s0, 2);
        s1 += __shfl_xor_sync(0xffffffffu, s1, 1);
        s1 += __shfl_xor_sync(0xffffffffu, s1, 2);
        l0v = l0v * al0 + s0;
        l1v = l1v * al1 + s1;
        #pragma unroll
        for (int j = 0; j < 8; j++) {
            oc[j][0] *= al0; oc[j][1] *= al0;
            oc[j][2] *= al1; oc[j][3] *= al1;
        }

        // ---- repack P (C-frag == A-frag layout) ----
        uint32_t pah[4][4], pal[4][4];
        #pragma unroll
        for (int t = 0; t < 4; t++) {
            pah[t][0] = packsplit(sc[2*t][0],   sc[2*t][1],   pal[t][0]);
            pah[t][1] = packsplit(sc[2*t][2],   sc[2*t][3],   pal[t][1]);
            pah[t][2] = packsplit(sc[2*t+1][0], sc[2*t+1][1], pal[t][2]);
            pah[t][3] = packsplit(sc[2*t+1][2], sc[2*t+1][3], pal[t][3]);
        }

        // ---- O += P V ----
        #pragma unroll
        for (int k16 = 0; k16 < 4; k16++) {
            uint32_t vh[8][2], vl[8][2];
            #pragma unroll
            for (int n16 = 0; n16 < 4; n16++) {
                uint32_t off = (uint32_t)((k16*16 + vrow)*FP_B + (n16*16 + vc8)*2);
                uint32_t r4[4];
                ldsm4t(r4, sVh + off);
                vh[2*n16][0] = r4[0]; vh[2*n16][1] = r4[1];
                vh[2*n16+1][0] = r4[2]; vh[2*n16+1][1] = r4[3];
                ldsm4t(r4, sVl + off);
                vl[2*n16][0] = r4[0]; vl[2*n16][1] = r4[1];
                vl[2*n16+1][0] = r4[2]; vl[2*n16+1][1] = r4[3];
            }
            #pragma unroll
            for (int j = 0; j < 8; j++) mma16816(oc[j], pah[k16], vh[j]);
            #pragma unroll
            for (int j = 0; j < 8; j++) mma16816(oc[j], pah[k16], vl[j]);
            #pragma unroll
            for (int j = 0; j < 8; j++) mma16816(oc[j], pal[k16], vh[j]);
        }

        if (++stage == 3) stage = 0;
    }

    // ---- finalize, write ctx bf16 hi/lo ----
    const float inv0 = 1.0f / l0v, inv1 = 1.0f / l1v;
    const int b = bh / NH, h = bh % NH;
    const int row0 = q0 + wm + (lane >> 2);
    #pragma unroll
    for (int j = 0; j < 8; j++) {
        int col = h*64 + j*8 + (lane & 3)*2;
        uint32_t lo;
        uint32_t hi = packsplit(oc[j][0]*inv0, oc[j][1]*inv0, lo);
        size_t off0 = ((size_t)(b*SB + row0))*DD + col;
        *(uint32_t*)&g_chi[off0] = hi;
        *(uint32_t*)&g_clo[off0] = lo;
        hi = packsplit(oc[j][2]*inv1, oc[j][3]*inv1, lo);
        size_t off1 = ((size_t)(b*SB + row0 + 8))*DD + col;
        *(uint32_t*)&g_chi[off1] = hi;
        *(uint32_t*)&g_clo[off1] = lo;
    }
}

// ---------------------------------------------------------------------------
extern "C" void kernel_launch(void* const* d_in, const int* in_sizes, int n_in,
                              void* d_out, int out_size)
{
    const float* x  = (const float*)d_in[0];
    const float* Wq = (const float*)d_in[1];
    const float* Wk = (const float*)d_in[2];
    const float* Wv = (const float*)d_in[3];
    const float* Wo = (const float*)d_in[4];
    const float* bo = (const float*)d_in[5];
    float* out = (float*)d_out;

    cudaFuncSetAttribute(qkv_gemm_mma,   cudaFuncAttributeMaxDynamicSharedMemorySize, GSMEM);
    cudaFuncSetAttribute(out_gemm_mma,   cudaFuncAttributeMaxDynamicSharedMemorySize, GSMEM);
    cudaFuncSetAttribute(flash_attn_mma, cudaFuncAttributeMaxDynamicSharedMemorySize, FA_SMEM);

    convert_split_all<<<dim3(160, 5), 256>>>(x, Wq, Wk, Wv, Wo);
    qkv_gemm_mma<<<dim3(24, 32), 256, GSMEM>>>();
    flash_attn_mma<<<dim3(SB/128, BB*NH), 256, FA_SMEM>>>();
    out_gemm_mma<<<dim3(8, 32), 256, GSMEM>>>(bo, out);
}

// round 10
// speedup vs baseline: 1.4024x; 1.1923x over previous
#include <cuda_runtime.h>
#include <cuda_bf16.h>
#include <cuda_fp16.h>
#include <math.h>
#include <stdint.h>

// Problem constants
#define SB   2048
#define BB   2
#define DD   1024
#define NH   16
#define HDIM 64
#define MR   (BB*SB)       // 4096

// Scratch (device globals)
// GEMM operands: fp16 (2-term scheme: A single, B hi+lo)
__device__ __align__(256) __half g_xh[(size_t)MR*DD];
__device__ __align__(256) __half g_wh[4][(size_t)DD*DD];
__device__ __align__(256) __half g_wl[4][(size_t)DD*DD];
__device__ __align__(256) __half g_ch[(size_t)MR*DD];          // ctx fp16
// Attention operands: bf16 hi/lo splits (3-term scheme, unchanged)
__device__ __align__(256) __nv_bfloat16 g_qhi[(size_t)MR*DD];  // [b,h,s,hd]
__device__ __align__(256) __nv_bfloat16 g_qlo[(size_t)MR*DD];
__device__ __align__(256) __nv_bfloat16 g_khi[(size_t)MR*DD];
__device__ __align__(256) __nv_bfloat16 g_klo[(size_t)MR*DD];
__device__ __align__(256) __nv_bfloat16 g_vhi[(size_t)MR*DD];
__device__ __align__(256) __nv_bfloat16 g_vlo[(size_t)MR*DD];

// ===========================================================================
// Helpers
// ===========================================================================
__device__ __forceinline__ uint32_t smem_u32(const void* p) {
    uint32_t a;
    asm("{ .reg .u64 t; cvta.to.shared.u64 t, %1; cvt.u32.u64 %0, t; }"
        : "=r"(a) : "l"(p));
    return a;
}

__device__ __forceinline__ void ldsm4(uint32_t* r, uint32_t a) {
    asm volatile("ldmatrix.sync.aligned.m8n8.x4.shared.b16 {%0,%1,%2,%3}, [%4];"
                 : "=r"(r[0]), "=r"(r[1]), "=r"(r[2]), "=r"(r[3]) : "r"(a));
}

__device__ __forceinline__ void ldsm4t(uint32_t* r, uint32_t a) {
    asm volatile("ldmatrix.sync.aligned.m8n8.x4.trans.shared.b16 {%0,%1,%2,%3}, [%4];"
                 : "=r"(r[0]), "=r"(r[1]), "=r"(r[2]), "=r"(r[3]) : "r"(a));
}

// bf16 mma (flash)
__device__ __forceinline__ void mma16816(float* c, const uint32_t* a, const uint32_t* b) {
    asm volatile(
        "mma.sync.aligned.m16n8k16.row.col.f32.bf16.bf16.f32 "
        "{%0,%1,%2,%3}, {%4,%5,%6,%7}, {%8,%9}, {%0,%1,%2,%3};"
        : "+f"(c[0]), "+f"(c[1]), "+f"(c[2]), "+f"(c[3])
        : "r"(a[0]), "r"(a[1]), "r"(a[2]), "r"(a[3]), "r"(b[0]), "r"(b[1]));
}

// fp16 mma (projection GEMMs)
__device__ __forceinline__ void mma16816h(float* c, const uint32_t* a, const uint32_t* b) {
    asm volatile(
        "mma.sync.aligned.m16n8k16.row.col.f32.f16.f16.f32 "
        "{%0,%1,%2,%3}, {%4,%5,%6,%7}, {%8,%9}, {%0,%1,%2,%3};"
        : "+f"(c[0]), "+f"(c[1]), "+f"(c[2]), "+f"(c[3])
        : "r"(a[0]), "r"(a[1]), "r"(a[2]), "r"(a[3]), "r"(b[0]), "r"(b[1]));
}

__device__ __forceinline__ void cp16(uint32_t dst, const void* src) {
    asm volatile("cp.async.cg.shared.global [%0], [%1], 16;"
                 :: "r"(dst), "l"(src) : "memory");
}
#define CP_COMMIT asm volatile("cp.async.commit_group;" ::: "memory")
#define CP_WAIT0  asm volatile("cp.async.wait_group 0;"  ::: "memory")
#define CP_WAIT1  asm volatile("cp.async.wait_group 1;"  ::: "memory")
#define CP_WAIT2  asm volatile("cp.async.wait_group 2;"  ::: "memory")

__device__ __forceinline__ uint32_t pack2(__nv_bfloat16 a, __nv_bfloat16 b) {
    __nv_bfloat162 t = __halves2bfloat162(a, b);
    return *(uint32_t*)&t;
}

// bf16 split pack (flash interface)
__device__ __forceinline__ uint32_t packsplit(float a, float b, uint32_t& lo) {
    __nv_bfloat16 ha = __float2bfloat16(a), hb = __float2bfloat16(b);
    lo = pack2(__float2bfloat16(a - __bfloat162float(ha)),
               __float2bfloat16(b - __bfloat162float(hb)));
    return pack2(ha, hb);
}

// fp16 split pack
__device__ __forceinline__ uint32_t packsplit_h(float a, float b, uint32_t& lo) {
    __half ha = __float2half_rn(a), hb = __float2half_rn(b);
    __half2 l = __halves2half2(__float2half_rn(a - __half2float(ha)),
                               __float2half_rn(b - __half2float(hb)));
    lo = *(uint32_t*)&l;
    __half2 h = __halves2half2(ha, hb);
    return *(uint32_t*)&h;
}

// ===========================================================================
// Convert: x -> fp16 single; W -> fp16 hi+lo. One launch, 5 segments.
// ===========================================================================
__global__ void convert_all(const float* __restrict__ x,
                            const float* __restrict__ Wq,
                            const float* __restrict__ Wk,
                            const float* __restrict__ Wv,
                            const float* __restrict__ Wo)
{
    const int seg = blockIdx.y;
    if (seg == 0) {
        // x -> fp16 single
        int n4 = MR*DD/4;
        for (int i = blockIdx.x * blockDim.x + threadIdx.x; i < n4;
             i += gridDim.x * blockDim.x) {
            float4 v = ((const float4*)x)[i];
            __half2 h01 = __floats2half2_rn(v.x, v.y);
            __half2 h23 = __floats2half2_rn(v.z, v.w);
            ((uint2*)g_xh)[i] = make_uint2(*(uint32_t*)&h01, *(uint32_t*)&h23);
        }
        return;
    }
    const float* src = (seg == 1) ? Wq : (seg == 2) ? Wk : (seg == 3) ? Wv : Wo;
    __half* hi = g_wh[seg-1];
    __half* lo = g_wl[seg-1];
    int n4 = DD*DD/4;
    for (int i = blockIdx.x * blockDim.x + threadIdx.x; i < n4;
         i += gridDim.x * blockDim.x) {
        float4 v = ((const float4*)src)[i];
        uint32_t l01, l23;
        uint32_t h01 = packsplit_h(v.x, v.y, l01);
        uint32_t h23 = packsplit_h(v.z, v.w, l23);
        ((uint2*)hi)[i] = make_uint2(h01, h23);
        ((uint2*)lo)[i] = make_uint2(l01, l23);
    }
}

// ===========================================================================
// fp16 2-term GEMM mainloop: D = A(fp16) * (Bh+Bl)^T, K-step 32, 3 stages,
// wait_group 1, XOR-swizzled 64B-pitch tiles (proven in round 9).
// Stage = 3 tiles (Ah, Bh, Bl). 64 MMAs per iteration.
// ===========================================================================
#define GP_B        64
#define TILE_B      (128*GP_B)          // 8192
#define STAGE_B     (3*TILE_B)          // 24576
#define GSMEM       (3*STAGE_B)         // 73728

__device__ __forceinline__ uint32_t gsw(int row, int chunk) {
    return (uint32_t)(row * GP_B + ((chunk ^ ((row >> 1) & 3)) << 4));
}

__device__ __forceinline__ void gemm_mainloop(
    const __half* __restrict__ A,
    const __half* __restrict__ Bh, const __half* __restrict__ Bl,
    int m0, int n0, char* sm, float acc[4][4][4])
{
    const int tid = threadIdx.x;
    const uint32_t smb = smem_u32(sm);

    #pragma unroll
    for (int t = 0; t < 4; t++)
        #pragma unroll
        for (int n = 0; n < 4; n++)
            #pragma unroll
            for (int e = 0; e < 4; e++) acc[t][n][e] = 0.0f;

    auto load_stage = [&](int st, int k0) {
        uint32_t base = smb + st * STAGE_B;
        #pragma unroll
        for (int j = 0; j < 2; j++) {
            int idx = tid + j * 256;
            int r = idx >> 2, c = idx & 3;
            uint32_t doff = gsw(r, c);
            size_t sa = (size_t)(m0 + r) * DD + k0 + c * 8;
            size_t sb = (size_t)(n0 + r) * DD + k0 + c * 8;
            cp16(base + doff,            A  + sa);
            cp16(base + TILE_B + doff,   Bh + sb);
            cp16(base + 2*TILE_B + doff, Bl + sb);
        }
    };

    load_stage(0, 0);  CP_COMMIT;
    load_stage(1, 32); CP_COMMIT;

    const int wid = tid >> 5, lane = tid & 31;
    const int wm = (wid >> 2) * 64;
    const int wn = (wid & 3) * 32;
    const int arow = lane & 15;
    const int ack  = lane >> 4;
    const int brow = (lane & 7) + ((lane >> 4) << 3);
    const int bck  = (lane >> 3) & 1;

    int stage = 0;
    for (int kt = 0; kt < 32; kt++) {
        CP_WAIT1;
        __syncthreads();
        if (kt + 2 < 32) {
            int st2 = stage + 2; if (st2 >= 3) st2 -= 3;
            load_stage(st2, (kt + 2) * 32);
            CP_COMMIT;
        }

        uint32_t base = smb + stage * STAGE_B;
        uint32_t sA = base, sBh = base + TILE_B, sBl = base + 2*TILE_B;

        #pragma unroll
        for (int k16 = 0; k16 < 2; k16++) {
            uint32_t ah[4][4], bh[4][2], bl[4][2];
            #pragma unroll
            for (int t = 0; t < 4; t++)
                ldsm4(ah[t], sA + gsw(wm + t*16 + arow, k16*2 + ack));
            #pragma unroll
            for (int p = 0; p < 2; p++) {
                uint32_t bo = gsw(wn + p*16 + brow, k16*2 + bck);
                uint32_t r4[4];
                ldsm4(r4, sBh + bo);
                bh[2*p][0] = r4[0]; bh[2*p][1] = r4[1];
                bh[2*p+1][0] = r4[2]; bh[2*p+1][1] = r4[3];
                ldsm4(r4, sBl + bo);
                bl[2*p][0] = r4[0]; bl[2*p][1] = r4[1];
                bl[2*p+1][0] = r4[2]; bl[2*p+1][1] = r4[3];
            }
            #pragma unroll
            for (int t = 0; t < 4; t++)
                #pragma unroll
                for (int n = 0; n < 4; n++)
                    mma16816h(acc[t][n], ah[t], bh[n]);
            #pragma unroll
            for (int t = 0; t < 4; t++)
                #pragma unroll
                for (int n = 0; n < 4; n++)
                    mma16816h(acc[t][n], ah[t], bl[n]);
        }

        if (++stage == 3) stage = 0;
    }
}

// ---------------------------------------------------------------------------
// QKV projection: writes q/k/v as bf16 hi/lo in [b,h,s,hd] (flash interface)
// ---------------------------------------------------------------------------
__global__ __launch_bounds__(256, 2) void qkv_gemm_mma()
{
    extern __shared__ char sm[];
    const int n0g = blockIdx.x * 128;
    const int m0  = blockIdx.y * 128;
    const int which = n0g >> 10;
    const int nb    = n0g & 1023;

    __nv_bfloat16* OH = (which == 0) ? g_qhi : (which == 1 ? g_khi : g_vhi);
    __nv_bfloat16* OL = (which == 0) ? g_qlo : (which == 1 ? g_klo : g_vlo);

    float acc[4][4][4];
    gemm_mainloop(g_xh, g_wh[which], g_wl[which], m0, nb, sm, acc);

    const int tid = threadIdx.x, wid = tid >> 5, lane = tid & 31;
    const int wm = (wid >> 2) * 64, wn = (wid & 3) * 32;
    const int gid = lane >> 2, qid = lane & 3;

    #pragma unroll
    for (int t = 0; t < 4; t++) {
        #pragma unroll
        for (int n = 0; n < 4; n++) {
            int cc = nb + wn + n*8 + qid*2;
            int h = cc >> 6, hd = cc & 63;
            #pragma unroll
            for (int half = 0; half < 2; half++) {
                int row = m0 + wm + t*16 + gid + 8*half;
                int b = row >> 11, s = row & 2047;
                uint32_t lo;
                uint32_t hi = packsplit(acc[t][n][2*half], acc[t][n][2*half+1], lo);
                size_t off = (((size_t)(b*NH + h))*SB + s)*HDIM + hd;
                *(uint32_t*)&OH[off] = hi;
                *(uint32_t*)&OL[off] = lo;
            }
        }
    }
}

// ---------------------------------------------------------------------------
// Output projection: out = ctx @ Wo^T + bo (fp32 out)
// ---------------------------------------------------------------------------
__global__ __launch_bounds__(256, 2) void out_gemm_mma(
    const float* __restrict__ bo, float* __restrict__ OUT)
{
    extern __shared__ char sm[];
    const int n0 = blockIdx.x * 128;
    const int m0 = blockIdx.y * 128;

    float acc[4][4][4];
    gemm_mainloop(g_ch, g_wh[3], g_wl[3], m0, n0, sm, acc);

    const int tid = threadIdx.x, wid = tid >> 5, lane = tid & 31;
    const int wm = (wid >> 2) * 64, wn = (wid & 3) * 32;
    const int gid = lane >> 2, qid = lane & 3;

    #pragma unroll
    for (int t = 0; t < 4; t++) {
        #pragma unroll
        for (int n = 0; n < 4; n++) {
            int cn = n0 + wn + n*8 + qid*2;
            float2 bb = *(const float2*)&bo[cn];
            #pragma unroll
            for (int half = 0; half < 2; half++) {
                int row = m0 + wm + t*16 + gid + 8*half;
                float2 v = make_float2(acc[t][n][2*half] + bb.x,
                                       acc[t][n][2*half + 1] + bb.y);
                *(float2*)&OUT[(size_t)row * DD + cn] = v;
            }
        }
    }
}

// ===========================================================================
// Flash attention on mma.sync (FA2-style, 3-term bf16 split) — unchanged core.
// exp via exp2f with folded log2(e); ctx written as fp16 single.
// ===========================================================================
#define FP_B  144                    // smem pitch bytes (72 halves, 16B mult)
#define BUF_B  (64*FP_B)             // 9216
#define STG_B  (4*BUF_B)             // 36864
#define FA_SMEM (3*STG_B)            // 110592
#define SCL2  0.18033688f            // 0.125 * log2(e)

__global__ __launch_bounds__(256, 2) void flash_attn_mma()
{
    extern __shared__ char smc[];
    const uint32_t smb = smem_u32(smc);

    const int qt = (int)gridDim.x - 1 - (int)blockIdx.x;   // heavy first
    const int bh = blockIdx.y;
    const int q0 = qt * 128;

    const int tid = threadIdx.x, w = tid >> 5, lane = tid & 31;
    const int wm = w * 16;

    const __nv_bfloat16* Qph = g_qhi + ((size_t)bh*SB + q0)*HDIM;
    const __nv_bfloat16* Qpl = g_qlo + ((size_t)bh*SB + q0)*HDIM;
    const __nv_bfloat16* Kph = g_khi + (size_t)bh*SB*HDIM;
    const __nv_bfloat16* Kpl = g_klo + (size_t)bh*SB*HDIM;
    const __nv_bfloat16* Vph = g_vhi + (size_t)bh*SB*HDIM;
    const __nv_bfloat16* Vpl = g_vlo + (size_t)bh*SB*HDIM;

    // ---- load Q (hi+lo) into stage-2 buffer ----
    const uint32_t QH_OFF = 2*STG_B;
    const uint32_t QL_OFF = 2*STG_B + 128*FP_B;
    for (int idx = tid; idx < 2048; idx += 256) {
        int buf = idx >> 10, r = (idx >> 3) & 127, c = idx & 7;
        cp16(smb + (buf ? QL_OFF : QH_OFF) + r*FP_B + c*16,
             (buf ? Qpl : Qph) + r*64 + c*8);
    }
    CP_COMMIT;

    auto load_kv = [&](int st, int c0) {
        uint32_t base = smb + st*STG_B;
        for (int idx = tid; idx < 2048; idx += 256) {
            int buf = idx >> 9, r = (idx >> 3) & 63, c = idx & 7;
            const __nv_bfloat16* sp =
                (buf == 0 ? Kph : buf == 1 ? Kpl : buf == 2 ? Vph : Vpl)
                + (size_t)(c0 + r)*64 + c*8;
            cp16(base + buf*BUF_B + r*FP_B + c*16, sp);
        }
    };

    const int nsteps = 2*(qt + 1);
    load_kv(0, 0);  CP_COMMIT;
    load_kv(1, 64); CP_COMMIT;

    CP_WAIT2;
    __syncthreads();

    const int arow = lane & 15;
    const int akk  = (lane >> 4) << 3;
    uint32_t qa[2][4][4];
    #pragma unroll
    for (int term = 0; term < 2; term++)
        #pragma unroll
        for (int t = 0; t < 4; t++)
            ldsm4(qa[term][t], smb + (term ? QL_OFF : QH_OFF)
                              + (wm + arow)*FP_B + (t*16 + akk)*2);

    float m0v = -INFINITY, m1v = -INFINITY, l0v = 0.0f, l1v = 0.0f;
    float oc[8][4];
    #pragma unroll
    for (int j = 0; j < 8; j++)
        #pragma unroll
        for (int e = 0; e < 4; e++) oc[j][e] = 0.0f;

    const int brow = (lane & 7) + ((lane >> 4) << 3);
    const int bkk  = ((lane >> 3) & 1) << 3;
    const int vrow = (lane & 7) + (((lane >> 3) & 1) << 3);
    const int vc8  = (lane >> 4) << 3;

    int stage = 0;
    for (int kt = 0; kt < nsteps; kt++) {
        const int c0 = kt * 64;
        CP_WAIT1;
        __syncthreads();
        if (kt + 2 < nsteps) {
            int st2 = stage + 2; if (st2 >= 3) st2 -= 3;
            load_kv(st2, (kt + 2)*64);
            CP_COMMIT;
        }

        const uint32_t sKh = smb + stage*STG_B;
        const uint32_t sKl = sKh + BUF_B;
        const uint32_t sVh = sKh + 2*BUF_B;
        const uint32_t sVl = sKh + 3*BUF_B;

        // ---- S = Q K^T ----
        float sc[8][4];
        #pragma unroll
        for (int j = 0; j < 8; j++)
            #pragma unroll
            for (int e = 0; e < 4; e++) sc[j][e] = 0.0f;

        #pragma unroll
        for (int k16 = 0; k16 < 4; k16++) {
            uint32_t kh[8][2], kl[8][2];
            #pragma unroll
            for (int j2 = 0; j2 < 4; j2++) {
                uint32_t off = (uint32_t)((j2*16 + brow)*FP_B + (k16*16 + bkk)*2);
                uint32_t r4[4];
                ldsm4(r4, sKh + off);
                kh[2*j2][0] = r4[0]; kh[2*j2][1] = r4[1];
                kh[2*j2+1][0] = r4[2]; kh[2*j2+1][1] = r4[3];
                ldsm4(r4, sKl + off);
                kl[2*j2][0] = r4[0]; kl[2*j2][1] = r4[1];
                kl[2*j2+1][0] = r4[2]; kl[2*j2+1][1] = r4[3];
            }
            #pragma unroll
            for (int j = 0; j < 8; j++) mma16816(sc[j], qa[0][k16], kh[j]);
            #pragma unroll
            for (int j = 0; j < 8; j++) mma16816(sc[j], qa[0][k16], kl[j]);
            #pragma unroll
            for (int j = 0; j < 8; j++) mma16816(sc[j], qa[1][k16], kh[j]);
        }

        // ---- scale (log2 domain) + causal mask ----
        const int r0 = q0 + wm + (lane >> 2);
        const bool needmask = (c0 + 64 > q0 + wm);
        #pragma unroll
        for (int j = 0; j < 8; j++) {
            int cb = c0 + j*8 + (lane & 3)*2;
            #pragma unroll
            for (int e = 0; e < 4; e++) {
                float v = sc[j][e] * SCL2;
                if (needmask) {
                    int col = cb + (e & 1);
                    int row = r0 + ((e >> 1) << 3);
                    if (col > row) v = -INFINITY;
                }
                sc[j][e] = v;
            }
        }

        // ---- online softmax (base-2) ----
        float mx0 = sc[0][0], mx1 = sc[0][2];
        #pragma unroll
        for (int j = 0; j < 8; j++) {
            mx0 = fmaxf(mx0, fmaxf(sc[j][0], sc[j][1]));
            mx1 = fmaxf(mx1, fmaxf(sc[j][2], sc[j][3]));
        }
        mx0 = fmaxf(mx0, __shfl_xor_sync(0xffffffffu, mx0, 1));
        mx0 = fmaxf(mx0, __shfl_xor_sync(0xffffffffu, mx0, 2));
        mx1 = fmaxf(mx1, __shfl_xor_sync(0xffffffffu, mx1, 1));
        mx1 = fmaxf(mx1, __shfl_xor_sync(0xffffffffu, mx1, 2));

        float mn0 = fmaxf(m0v, mx0), mn1 = fmaxf(m1v, mx1);
        float al0 = exp2f(m0v - mn0), al1 = exp2f(m1v - mn1);
        m0v = mn0; m1v = mn1;

        float s0 = 0.0f, s1 = 0.0f;
        #pragma unroll
        for (int j = 0; j < 8; j++) {
            sc[j][0] = exp2f(sc[j][0] - mn0); s0 += sc[j][0];
            sc[j][1] = exp2f(sc[j][1] - mn0); s0 += sc[j][1];
            sc[j][2] = exp2f(sc[j][2] - mn1); s1 += sc[j][2];
            sc[j][3] = exp2f(sc[j][3] - mn1); s1 += sc[j][3];
        }
        s0 += __shfl_xor_sync(0xffffffffu, s0, 1);
        s0 += __shfl_xor_sync(0xffffffffu, s0, 2);
        s1 += __shfl_xor_sync(0xffffffffu, s1, 1);
        s1 += __shfl_xor_sync(0xffffffffu, s1, 2);
        l0v = l0v * al0 + s0;
        l1v = l1v * al1 + s1;
        #pragma unroll
        for (int j = 0; j < 8; j++) {
            oc[j][0] *= al0; oc[j][1] *= al0;
            oc[j][2] *= al1; oc[j][3] *= al1;
        }

        // ---- repack P (C-frag == A-frag layout) ----
        uint32_t pah[4][4], pal[4][4];
        #pragma unroll
        for (int t = 0; t < 4; t++) {
            pah[t][0] = packsplit(sc[2*t][0],   sc[2*t][1],   pal[t][0]);
            pah[t][1] = packsplit(sc[2*t][2],   sc[2*t][3],   pal[t][1]);
            pah[t][2] = packsplit(sc[2*t+1][0], sc[2*t+1][1], pal[t][2]);
            pah[t][3] = packsplit(sc[2*t+1][2], sc[2*t+1][3], pal[t][3]);
        }

        // ---- O += P V ----
        #pragma unroll
        for (int k16 = 0; k16 < 4; k16++) {
            uint32_t vh[8][2], vl[8][2];
            #pragma unroll
            for (int n16 = 0; n16 < 4; n16++) {
                uint32_t off = (uint32_t)((k16*16 + vrow)*FP_B + (n16*16 + vc8)*2);
                uint32_t r4[4];
                ldsm4t(r4, sVh + off);
                vh[2*n16][0] = r4[0]; vh[2*n16][1] = r4[1];
                vh[2*n16+1][0] = r4[2]; vh[2*n16+1][1] = r4[3];
                ldsm4t(r4, sVl + off);
                vl[2*n16][0] = r4[0]; vl[2*n16][1] = r4[1];
                vl[2*n16+1][0] = r4[2]; vl[2*n16+1][1] = r4[3];
            }
            #pragma unroll
            for (int j = 0; j < 8; j++) mma16816(oc[j], pah[k16], vh[j]);
            #pragma unroll
            for (int j = 0; j < 8; j++) mma16816(oc[j], pah[k16], vl[j]);
            #pragma unroll
            for (int j = 0; j < 8; j++) mma16816(oc[j], pal[k16], vh[j]);
        }

        if (++stage == 3) stage = 0;
    }

    // ---- finalize, write ctx as fp16 (out_gemm A operand) ----
    const float inv0 = 1.0f / l0v, inv1 = 1.0f / l1v;
    const int b = bh / NH, h = bh % NH;
    const int row0 = q0 + wm + (lane >> 2);
    #pragma unroll
    for (int j = 0; j < 8; j++) {
        int col = h*64 + j*8 + (lane & 3)*2;
        __half2 h0 = __floats2half2_rn(oc[j][0]*inv0, oc[j][1]*inv0);
        size_t off0 = ((size_t)(b*SB + row0))*DD + col;
        *(uint32_t*)&g_ch[off0] = *(uint32_t*)&h0;
        __half2 h1 = __floats2half2_rn(oc[j][2]*inv1, oc[j][3]*inv1);
        size_t off1 = ((size_t)(b*SB + row0 + 8))*DD + col;
        *(uint32_t*)&g_ch[off1] = *(uint32_t*)&h1;
    }
}

// ---------------------------------------------------------------------------
extern "C" void kernel_launch(void* const* d_in, const int* in_sizes, int n_in,
                              void* d_out, int out_size)
{
    const float* x  = (const float*)d_in[0];
    const float* Wq = (const float*)d_in[1];
    const float* Wk = (const float*)d_in[2];
    const float* Wv = (const float*)d_in[3];
    const float* Wo = (const float*)d_in[4];
    const float* bo = (const float*)d_in[5];
    float* out = (float*)d_out;

    cudaFuncSetAttribute(qkv_gemm_mma,   cudaFuncAttributeMaxDynamicSharedMemorySize, GSMEM);
    cudaFuncSetAttribute(out_gemm_mma,   cudaFuncAttributeMaxDynamicSharedMemorySize, GSMEM);
    cudaFuncSetAttribute(flash_attn_mma, cudaFuncAttributeMaxDynamicSharedMemorySize, FA_SMEM);

    convert_all<<<dim3(160, 5), 256>>>(x, Wq, Wk, Wv, Wo);
    qkv_gemm_mma<<<dim3(24, 32), 256, GSMEM>>>();
    flash_attn_mma<<<dim3(SB/128, BB*NH), 256, FA_SMEM>>>();
    out_gemm_mma<<<dim3(8, 32), 256, GSMEM>>>(bo, out);
}